// round 1
// baseline (speedup 1.0000x reference)
#include <cuda_runtime.h>

// Tiny transformer block, one warp per batch item.
// T=8 tokens, C=32 embed, 4 heads x 8 head-dim, FF=128.
//
// All weights live in shared memory, transposed ([out_col][k]) and
// chunk-XOR-swizzled so per-column float4 reads are bank-conflict free.
// Per-warp activation scratch uses padded strides (36 / 100 / 132) so
// broadcast float4 reads across t are conflict-free.

#define TT 8
#define CC 32
#define FF2K 128

// shared memory layout (in floats)
#define OFF_WQKV  0        // 96 cols x 32 k  = 3072
#define OFF_WPROJ 3072     // 32 x 32         = 1024
#define OFF_WFF1  4096     // 128 x 32        = 4096
#define OFF_WFF2  8192     // 32 x 128        = 4096
#define OFF_WARP  12288
#define WARP_FLOATS 1664   // per-warp scratch
// per-warp scratch layout:
#define OFF_XS 0           // [8][36]
#define OFF_YS 288         // [8][36]
#define OFF_SC 576         // 1088-float union: {qkv[8][100], a[8][36]} then H[8][132]
#define SMEM_FLOATS (12288 + 8 * 1664)   // 25600 floats = 100 KB

__device__ __forceinline__ int swz(int k, int col) {
    // chunk-XOR swizzle: keeps 4-float chunks contiguous, rotates chunk slot
    return ((((k >> 2) ^ (col & 7)) << 2) | (k & 3));
}

__device__ __forceinline__ float dot4fma(float4 x, float4 w, float acc) {
    acc = fmaf(x.x, w.x, acc);
    acc = fmaf(x.y, w.y, acc);
    acc = fmaf(x.z, w.z, acc);
    acc = fmaf(x.w, w.w, acc);
    return acc;
}

__global__ void __launch_bounds__(256, 2)
block_kernel(const float* __restrict__ Xg,
             const float* __restrict__ Wattn,   // [4][32][24]
             const float* __restrict__ Wproj,   // [32][32] (in,out)
             const float* __restrict__ Wff1,    // [32][128]
             const float* __restrict__ Wff2,    // [128][32]
             float* __restrict__ Out,
             int b)
{
    extern __shared__ float sm[];
    const int tid = threadIdx.x;

    // ---- stage weights (transposed + swizzled), once per block ----
    for (int idx = tid; idx < 96 * 32; idx += 256) {
        int col = idx >> 5, k = idx & 31;
        int h = col / 24, d = col - h * 24;         // col = h*24 + d
        sm[OFF_WQKV + col * 32 + swz(k, col)] = Wattn[h * 768 + k * 24 + d];
    }
    for (int idx = tid; idx < 32 * 32; idx += 256) {
        int col = idx >> 5, k = idx & 31;
        sm[OFF_WPROJ + col * 32 + swz(k, col)] = Wproj[k * 32 + col];
    }
    for (int idx = tid; idx < 128 * 32; idx += 256) {
        int col = idx >> 5, k = idx & 31;
        sm[OFF_WFF1 + col * 32 + swz(k, col)] = Wff1[k * 128 + col];
    }
    for (int idx = tid; idx < 32 * 128; idx += 256) {
        int col = idx >> 7, k = idx & 127;
        sm[OFF_WFF2 + col * 128 + swz(k, col)] = Wff2[k * 32 + col];
    }
    __syncthreads();

    const int warp = tid >> 5;
    const int lane = tid & 31;
    float* ws = sm + OFF_WARP + warp * WARP_FLOATS;
    float* Xs = ws + OFF_XS;   // [8][36]
    float* Ys = ws + OFF_YS;   // [8][36]
    float* SC = ws + OFF_SC;   // scratch union

    const int nwarps = (gridDim.x * blockDim.x) >> 5;
    for (int it = (blockIdx.x * blockDim.x + tid) >> 5; it < b; it += nwarps) {

        // ---- load X (8x32) into Xs, stride 36 ----
        const float4* Xi = (const float4*)(Xg + (size_t)it * 256);
        #pragma unroll
        for (int r = 0; r < 2; r++) {
            int e4 = lane + 32 * r;               // float4 index 0..63
            float4 v = Xi[e4];
            int t = e4 >> 3, k4 = (e4 & 7) << 2;
            *(float4*)&Xs[t * 36 + k4] = v;
        }
        __syncwarp();

        // ---- fused QKV: X(8x32) @ Wcat(32x96); lane owns cols lane, lane+32, lane+64 ----
        {
            float acc[8][3];
            #pragma unroll
            for (int t = 0; t < 8; t++) { acc[t][0] = 0.f; acc[t][1] = 0.f; acc[t][2] = 0.f; }
            const float* Wq = sm + OFF_WQKV;
            const int sw7 = lane & 7;
            #pragma unroll
            for (int kc = 0; kc < 8; kc++) {
                const int cs = ((kc ^ sw7) << 2);
                float4 w0 = *(const float4*)&Wq[(lane      ) * 32 + cs];
                float4 w1 = *(const float4*)&Wq[(lane + 32 ) * 32 + cs];
                float4 w2 = *(const float4*)&Wq[(lane + 64 ) * 32 + cs];
                #pragma unroll
                for (int t = 0; t < 8; t++) {
                    float4 x = *(const float4*)&Xs[t * 36 + (kc << 2)];
                    acc[t][0] = dot4fma(x, w0, acc[t][0]);
                    acc[t][1] = dot4fma(x, w1, acc[t][1]);
                    acc[t][2] = dot4fma(x, w2, acc[t][2]);
                }
            }
            float* qk = SC;   // [8][100], col = h*24+d (K:0-7, Q:8-15, V:16-23)
            #pragma unroll
            for (int t = 0; t < 8; t++) {
                qk[t * 100 + lane      ] = acc[t][0];
                qk[t * 100 + lane + 32 ] = acc[t][1];
                qk[t * 100 + lane + 64 ] = acc[t][2];
            }
        }
        __syncwarp();

        // ---- attention: lane = h*8 + t1 ----
        {
            const int h = lane >> 3, t1 = lane & 7;
            const float* base = SC + h * 24;
            float4 q0 = *(const float4*)&base[t1 * 100 + 8];
            float4 q1 = *(const float4*)&base[t1 * 100 + 12];
            float s[8];
            float m = -1e30f;
            #pragma unroll
            for (int t2 = 0; t2 < 8; t2++) {
                float4 k0 = *(const float4*)&base[t2 * 100];
                float4 k1 = *(const float4*)&base[t2 * 100 + 4];
                float d = q0.x * k0.x + q0.y * k0.y + q0.z * k0.z + q0.w * k0.w
                        + q1.x * k1.x + q1.y * k1.y + q1.z * k1.z + q1.w * k1.w;
                d *= 0.17677669529663687f;          // 32^-0.5 (full embed dim, as in ref)
                d = (t2 <= t1) ? d : -1e30f;        // causal
                s[t2] = d;
                m = fmaxf(m, d);
            }
            float sum = 0.f;
            #pragma unroll
            for (int t2 = 0; t2 < 8; t2++) {
                float e = __expf(s[t2] - m);
                e = (t2 <= t1) ? e : 0.f;
                s[t2] = e;
                sum += e;
            }
            float inv = __fdividef(1.f, sum);
            float a[8];
            #pragma unroll
            for (int d = 0; d < 8; d++) a[d] = 0.f;
            #pragma unroll
            for (int t2 = 0; t2 < 8; t2++) {
                float wt = s[t2];
                float4 v0 = *(const float4*)&base[t2 * 100 + 16];
                float4 v1 = *(const float4*)&base[t2 * 100 + 20];
                a[0] = fmaf(wt, v0.x, a[0]); a[1] = fmaf(wt, v0.y, a[1]);
                a[2] = fmaf(wt, v0.z, a[2]); a[3] = fmaf(wt, v0.w, a[3]);
                a[4] = fmaf(wt, v1.x, a[4]); a[5] = fmaf(wt, v1.y, a[5]);
                a[6] = fmaf(wt, v1.z, a[6]); a[7] = fmaf(wt, v1.w, a[7]);
            }
            float* as_ = SC + 800;   // [8][36], concat layout [t][h*8+d]
            float4 o0 = make_float4(a[0] * inv, a[1] * inv, a[2] * inv, a[3] * inv);
            float4 o1 = make_float4(a[4] * inv, a[5] * inv, a[6] * inv, a[7] * inv);
            *(float4*)&as_[t1 * 36 + h * 8    ] = o0;
            *(float4*)&as_[t1 * 36 + h * 8 + 4] = o1;
        }
        __syncwarp();

        // ---- proj + residual: Y = X + A @ Wproj; lane = out col ----
        {
            const float* as_ = SC + 800;
            const float* Wp = sm + OFF_WPROJ;
            const int sw7 = lane & 7;
            float acc[8];
            #pragma unroll
            for (int t = 0; t < 8; t++) acc[t] = Xs[t * 36 + lane];
            #pragma unroll
            for (int kc = 0; kc < 8; kc++) {
                float4 w = *(const float4*)&Wp[lane * 32 + ((kc ^ sw7) << 2)];
                #pragma unroll
                for (int t = 0; t < 8; t++) {
                    float4 x = *(const float4*)&as_[t * 36 + (kc << 2)];
                    acc[t] = dot4fma(x, w, acc[t]);
                }
            }
            #pragma unroll
            for (int t = 0; t < 8; t++) Ys[t * 36 + lane] = acc[t];
        }
        __syncwarp();

        // ---- FF1: H = relu(Y @ Wff1); lane owns cols lane+32j ----
        float* Hs = SC;   // [8][132], overwrites qkv/a scratch (dead)
        {
            const float* W1 = sm + OFF_WFF1;
            const int sw7 = lane & 7;
            float f[8][4];
            #pragma unroll
            for (int t = 0; t < 8; t++) {
                f[t][0] = 0.f; f[t][1] = 0.f; f[t][2] = 0.f; f[t][3] = 0.f;
            }
            #pragma unroll
            for (int kc = 0; kc < 8; kc++) {
                const int cs = ((kc ^ sw7) << 2);
                float4 w0 = *(const float4*)&W1[(lane      ) * 32 + cs];
                float4 w1 = *(const float4*)&W1[(lane + 32 ) * 32 + cs];
                float4 w2 = *(const float4*)&W1[(lane + 64 ) * 32 + cs];
                float4 w3 = *(const float4*)&W1[(lane + 96 ) * 32 + cs];
                #pragma unroll
                for (int t = 0; t < 8; t++) {
                    float4 x = *(const float4*)&Ys[t * 36 + (kc << 2)];
                    f[t][0] = dot4fma(x, w0, f[t][0]);
                    f[t][1] = dot4fma(x, w1, f[t][1]);
                    f[t][2] = dot4fma(x, w2, f[t][2]);
                    f[t][3] = dot4fma(x, w3, f[t][3]);
                }
            }
            #pragma unroll
            for (int t = 0; t < 8; t++) {
                Hs[t * 132 + lane      ] = fmaxf(f[t][0], 0.f);
                Hs[t * 132 + lane + 32 ] = fmaxf(f[t][1], 0.f);
                Hs[t * 132 + lane + 64 ] = fmaxf(f[t][2], 0.f);
                Hs[t * 132 + lane + 96 ] = fmaxf(f[t][3], 0.f);
            }
        }
        __syncwarp();

        // ---- FF2 + residual + store: out = Y + H @ Wff2 ----
        {
            const float* W2 = sm + OFF_WFF2;
            const int sw7 = lane & 7;
            float acc[8];
            #pragma unroll
            for (int t = 0; t < 8; t++) acc[t] = Ys[t * 36 + lane];
            #pragma unroll
            for (int jc = 0; jc < 32; jc++) {
                float4 w = *(const float4*)&W2[lane * 128 + ((jc ^ sw7) << 2)];
                #pragma unroll
                for (int t = 0; t < 8; t++) {
                    float4 hv = *(const float4*)&Hs[t * 132 + (jc << 2)];
                    acc[t] = dot4fma(hv, w, acc[t]);
                }
            }
            float* Og = Out + (size_t)it * 256;
            #pragma unroll
            for (int t = 0; t < 8; t++) Og[t * 32 + lane] = acc[t];
        }
        __syncwarp();   // scratch reused next iteration
    }
}

extern "C" void kernel_launch(void* const* d_in, const int* in_sizes, int n_in,
                              void* d_out, int out_size) {
    const float* X     = (const float*)d_in[0];
    const float* Wattn = (const float*)d_in[1];
    const float* Wproj = (const float*)d_in[2];
    const float* Wff1  = (const float*)d_in[3];
    const float* Wff2  = (const float*)d_in[4];
    float* out = (float*)d_out;

    int b = in_sizes[0] / 256;           // items = elements / (T*C)
    int smem_bytes = SMEM_FLOATS * (int)sizeof(float);   // 102400

    cudaFuncSetAttribute(block_kernel,
                         cudaFuncAttributeMaxDynamicSharedMemorySize, smem_bytes);

    int blocks = (b + 7) / 8;            // one item per warp, 8 warps/block
    block_kernel<<<blocks, 256, smem_bytes>>>(X, Wattn, Wproj, Wff1, Wff2, out, b);
    (void)n_in; (void)out_size;
}